// round 4
// baseline (speedup 1.0000x reference)
#include <cuda_runtime.h>
#include <cuda_bf16.h>

#define M_Q   1024
#define N_T   8192
#define CDIM  256
#define OT_ITERS 1000
#define MARGIN_V 0.7f
#define NBLK 128
#define NTHR 256
#define RENORM_PERIOD 16

// Static scratch (no runtime allocation allowed)
__device__ float g_K[M_Q * N_T];     // 32 MB kernel matrix (L2-resident)
__device__ float g_a[M_Q];
__device__ float g_b[N_T];
__device__ float g_t[N_T];           // ||T_j||^2
__device__ float g_rmax[M_Q];
__device__ float g_cmax[N_T];
__device__ float g_R[M_Q * CDIM];    // P @ T
__device__ float g_rn[M_Q];          // per-row norms

// Software grid barrier state
__device__ volatile unsigned g_bar_gen;
__device__ unsigned g_bar_cnt;

__device__ __forceinline__ void grid_bar() {
    __syncthreads();
    if (threadIdx.x == 0) {
        __threadfence();
        unsigned gen = g_bar_gen;
        unsigned old = atomicInc(&g_bar_cnt, NBLK - 1);
        if (old == NBLK - 1) {
            __threadfence();
            g_bar_gen = gen + 1;
        } else {
            while (g_bar_gen == gen) __nanosleep(64);
        }
    }
    __syncthreads();
}

__device__ __forceinline__ float4 ldcg4(const float4* p) { return __ldcg(p); }

// ---------------------------------------------------------------------------
// t_j = sum_c T[j][c]^2
__global__ void k_t(const float* __restrict__ x) {
    int j = blockIdx.x * blockDim.x + threadIdx.x;     // 0..8191
    int img = j >> 10, p = j & 1023;
    const float* base = x + (size_t)(img + 1) * CDIM * 1024 + p;
    float s = 0.f;
#pragma unroll 8
    for (int c = 0; c < CDIM; c++) { float v = base[c * 1024]; s += v * v; }
    g_t[j] = s;
}

// ---------------------------------------------------------------------------
// D[i][j] = t_j - 2 * sum_c Q[i][c]*T[j][c]   (written into g_K)
__global__ void k_gemm(const float* __restrict__ x) {
    __shared__ float As[16][64];
    __shared__ float Bs[16][64];
    int i0 = blockIdx.y * 64;
    int j0 = blockIdx.x * 64;
    int img = j0 >> 10, p0 = j0 & 1023;
    const float* A = x;                                   // Q: [c*1024 + i]
    const float* B = x + (size_t)(img + 1) * CDIM * 1024; // T: [c*1024 + p]
    int tx = threadIdx.x, ty = threadIdx.y;
    int t = ty * 16 + tx;
    float acc[4][4] = {};
    for (int k0 = 0; k0 < CDIM; k0 += 16) {
#pragma unroll
        for (int s = 0; s < 4; s++) {
            int e = t + s * 256;
            int cl = e >> 6, il = e & 63;
            As[cl][il] = A[(size_t)(k0 + cl) * 1024 + i0 + il];
            Bs[cl][il] = B[(size_t)(k0 + cl) * 1024 + p0 + il];
        }
        __syncthreads();
#pragma unroll
        for (int c = 0; c < 16; c++) {
            float ra[4], rb[4];
#pragma unroll
            for (int u = 0; u < 4; u++) ra[u] = As[c][ty * 4 + u];
#pragma unroll
            for (int v = 0; v < 4; v++) rb[v] = Bs[c][tx * 4 + v];
#pragma unroll
            for (int u = 0; u < 4; u++)
#pragma unroll
                for (int v = 0; v < 4; v++) acc[u][v] += ra[u] * rb[v];
        }
        __syncthreads();
    }
#pragma unroll
    for (int u = 0; u < 4; u++) {
        int i = i0 + ty * 4 + u;
#pragma unroll
        for (int v = 0; v < 4; v++) {
            int j = j0 + tx * 4 + v;
            g_K[(size_t)i * N_T + j] = g_t[j] - 2.f * acc[u][v];
        }
    }
}

// ---------------------------------------------------------------------------
// Row max of D
__global__ void k_rmax() {
    int i = blockIdx.x;
    const float* row = g_K + (size_t)i * N_T;
    int tid = threadIdx.x;
    float m = -1e30f;
    for (int j = tid; j < N_T; j += 256) m = fmaxf(m, row[j]);
    __shared__ float sm[256];
    sm[tid] = m; __syncthreads();
    for (int s = 128; s > 0; s >>= 1) {
        if (tid < s) sm[tid] = fmaxf(sm[tid], sm[tid + s]);
        __syncthreads();
    }
    if (tid == 0) g_rmax[i] = sm[0];
}

// Column max of (D - rmax)
__global__ void k_cmax() {
    int j = blockIdx.x * 256 + threadIdx.x;
    float m = -1e30f;
    for (int i = 0; i < M_Q; i++)
        m = fmaxf(m, g_K[(size_t)i * N_T + j] - g_rmax[i]);
    g_cmax[j] = m;
}

// K = exp(D - rmax_i - cmax_j); all exponents <= 0 (cmax_j >= D_ij - rmax_i).
__global__ void k_exp() {
    int i = blockIdx.x;
    float* row = g_K + (size_t)i * N_T;
    float rm = g_rmax[i];
    for (int j = threadIdx.x; j < N_T; j += 256)
        row[j] = __expf(row[j] - rm - g_cmax[j]);
}

// init b_j = exp(cmax_j)  <=>  reference v=0 start; reset barrier state.
// Every row's argmax column j* has cmax_{j*}=0, so K_{i,j*} b_{j*} = 1 and
// every row sum >= 1 at iteration 1.
__global__ void k_init() {
    int j = blockIdx.x * blockDim.x + threadIdx.x;
    g_b[j] = __expf(g_cmax[j]);
    if (j == 0) { g_bar_cnt = 0; g_bar_gen = 0; }
}

// ---------------------------------------------------------------------------
// Persistent Sinkhorn loop (scaling form, exp-free).
// Phase A: block owns 8 rows -> a_i = mu_i / (K[i,:].b)
// Phase B: block owns 64 cols -> b_j = nu_j / (K[:,j].a)
// All cross-block-shared data accessed via .cg (L2-coherent; per-SM L1 is
// NOT coherent across blocks within one launch).
// Inconsistent marginal sums (sum nu / sum mu ~ 8) make a,b drift x8 per
// iteration -> renorm K <- diag(a) K diag(b), b <- 1 every 16 iters.
__global__ void __launch_bounds__(NTHR, 1) k_loop(const float* __restrict__ att) {
    int bid = blockIdx.x, tid = threadIdx.x;
    __shared__ float a_sh[M_Q];
    __shared__ float red[8][9];
    __shared__ float redB[4][64];
    int i0 = bid * 8;
    int lane = tid & 31, warp = tid >> 5;

    for (int it = 0; it < OT_ITERS; ++it) {
        // ---- Phase A ----
        {
            const float4* b4 = (const float4*)g_b;
            const float4* K4 = (const float4*)(g_K + (size_t)i0 * N_T);
            float acc[8] = {};
            for (int j = tid; j < N_T / 4; j += NTHR) {
                float4 bb = ldcg4(b4 + j);
#pragma unroll
                for (int r = 0; r < 8; r++) {
                    float4 k = ldcg4(K4 + r * (N_T / 4) + j);
                    acc[r] += k.x * bb.x + k.y * bb.y + k.z * bb.z + k.w * bb.w;
                }
            }
#pragma unroll
            for (int r = 0; r < 8; r++) {
                float v = acc[r];
                v += __shfl_xor_sync(0xffffffffu, v, 16);
                v += __shfl_xor_sync(0xffffffffu, v, 8);
                v += __shfl_xor_sync(0xffffffffu, v, 4);
                v += __shfl_xor_sync(0xffffffffu, v, 2);
                v += __shfl_xor_sync(0xffffffffu, v, 1);
                if (lane == 0) red[r][warp] = v;
            }
            __syncthreads();
            if (tid < 8) {
                float s = 0.f;
#pragma unroll
                for (int w = 0; w < 8; w++) s += red[tid][w];
                __stcg(&g_a[i0 + tid], att[i0 + tid] / s);
            }
        }
        grid_bar();

        // ---- Phase B ----
        {
            for (int i = tid; i < M_Q; i += NTHR) a_sh[i] = __ldcg(&g_a[i]);
            __syncthreads();
            int c = tid & 63;
            int rg = tid >> 6;  // 0..3, 256 rows each
            int j = bid * 64 + c;
            float s = 0.f;
            const float* Kc = g_K + (size_t)(rg * 256) * N_T + j;
            const float* av = a_sh + rg * 256;
#pragma unroll 8
            for (int r = 0; r < 256; r++)
                s += __ldcg(Kc + (size_t)r * N_T) * av[r];
            redB[rg][c] = s;
            __syncthreads();
            if (tid < 64) {
                float t2 = redB[0][tid] + redB[1][tid] + redB[2][tid] + redB[3][tid];
                __stcg(&g_b[bid * 64 + tid], att[M_Q + bid * 64 + tid] / t2);
            }
        }
        grid_bar();

        // ---- periodic renorm: K <- diag(a) K diag(b); b <- 1 ----
        if (((it + 1) % RENORM_PERIOD) == 0 && it != OT_ITERS - 1) {
            const float4* bb4 = (const float4*)g_b;
#pragma unroll
            for (int r = 0; r < 8; r++) {
                float av = __ldcg(&g_a[i0 + r]);
                float4* row = (float4*)(g_K + (size_t)(i0 + r) * N_T);
                for (int j4 = tid; j4 < N_T / 4; j4 += NTHR) {
                    float4 v = ldcg4(row + j4), b = ldcg4(bb4 + j4);
                    v.x *= av * b.x; v.y *= av * b.y;
                    v.z *= av * b.z; v.w *= av * b.w;
                    __stcg(row + j4, v);
                }
            }
            grid_bar();
            if (tid < 64) __stcg(&g_b[bid * 64 + tid], 1.f);
            grid_bar();
        }
    }
}

// ---------------------------------------------------------------------------
// Epilogue GEMM: R[i][c] = a_i * sum_j K[i][j]*b_j * T[j][c]
__global__ void k_pt(const float* __restrict__ x) {
    __shared__ float Ks[64][68];
    __shared__ float Ts[64][68];
    int c0 = blockIdx.x * 64;
    int i0 = blockIdx.y * 64;
    int tx = threadIdx.x, ty = threadIdx.y;
    int t = ty * 16 + tx;
    float acc[4][4] = {};
    for (int jt = 0; jt < N_T / 64; jt++) {
        int j0 = jt * 64;
        int img = j0 >> 10, p0 = j0 & 1023;
        const float* Tbase = x + (size_t)(img + 1) * CDIM * 1024;
#pragma unroll
        for (int s = 0; s < 16; s++) {
            int e = t + s * 256;
            int jj = e & 63, r = e >> 6;
            Ks[jj][r] = g_K[(size_t)(i0 + r) * N_T + j0 + jj] * g_b[j0 + jj];
            Ts[jj][r] = Tbase[(size_t)(c0 + r) * 1024 + p0 + jj];
        }
        __syncthreads();
#pragma unroll
        for (int jj = 0; jj < 64; jj++) {
            float4 ra = *(const float4*)&Ks[jj][ty * 4];
            float4 rb = *(const float4*)&Ts[jj][tx * 4];
            acc[0][0] += ra.x * rb.x; acc[0][1] += ra.x * rb.y; acc[0][2] += ra.x * rb.z; acc[0][3] += ra.x * rb.w;
            acc[1][0] += ra.y * rb.x; acc[1][1] += ra.y * rb.y; acc[1][2] += ra.y * rb.z; acc[1][3] += ra.y * rb.w;
            acc[2][0] += ra.z * rb.x; acc[2][1] += ra.z * rb.y; acc[2][2] += ra.z * rb.z; acc[2][3] += ra.z * rb.w;
            acc[3][0] += ra.w * rb.x; acc[3][1] += ra.w * rb.y; acc[3][2] += ra.w * rb.z; acc[3][3] += ra.w * rb.w;
        }
        __syncthreads();
    }
#pragma unroll
    for (int u = 0; u < 4; u++) {
        int i = i0 + ty * 4 + u;
        float a = g_a[i];
#pragma unroll
        for (int v = 0; v < 4; v++)
            g_R[(size_t)i * CDIM + c0 + tx * 4 + v] = a * acc[u][v];
    }
}

// diff[i][c] = mu_i*Q[i][c] - R[i][c];  g_rn[i] = ||diff[i,:]||
__global__ void k_norm(const float* __restrict__ x, const float* __restrict__ att) {
    int i = blockIdx.x;
    int c = threadIdx.x;
    float mu = att[i];
    float q = x[(size_t)c * 1024 + i];
    float d = mu * q - g_R[(size_t)i * CDIM + c];
    __shared__ float sm[256];
    sm[c] = d * d; __syncthreads();
    for (int s = 128; s > 0; s >>= 1) {
        if (c < s) sm[c] += sm[c + s];
        __syncthreads();
    }
    if (c == 0) g_rn[i] = sqrtf(sm[0]);
}

__global__ void k_final(const int* __restrict__ label, float* __restrict__ out) {
    __shared__ float sm[1024];
    int tid = threadIdx.x;
    sm[tid] = g_rn[tid]; __syncthreads();
    for (int s = 512; s > 0; s >>= 1) {
        if (tid < s) sm[tid] += sm[tid + s];
        __syncthreads();
    }
    if (tid == 0) {
        float d = sm[0];
        out[0] = (*label) ? d : fmaxf(MARGIN_V - d, 0.f);
    }
}

// ---------------------------------------------------------------------------
extern "C" void kernel_launch(void* const* d_in, const int* in_sizes, int n_in,
                              void* d_out, int out_size) {
    const float* x     = (const float*)d_in[0];
    const float* att   = (const float*)d_in[1];
    const int*   label = (const int*)d_in[2];
    float* out = (float*)d_out;

    // Setup
    k_t<<<32, 256>>>(x);
    k_gemm<<<dim3(N_T / 64, M_Q / 64), dim3(16, 16)>>>(x);
    k_rmax<<<M_Q, 256>>>();
    k_cmax<<<N_T / 256, 256>>>();
    k_exp<<<M_Q, 256>>>();
    k_init<<<32, 256>>>();

    // Entire 1000-iteration Sinkhorn loop in ONE persistent kernel
    k_loop<<<NBLK, NTHR>>>(att);

    // Epilogue
    k_pt<<<dim3(CDIM / 64, M_Q / 64), dim3(16, 16)>>>(x);
    k_norm<<<M_Q, 256>>>(x, att);
    k_final<<<1, 1024>>>(label, out);
}